// round 3
// baseline (speedup 1.0000x reference)
#include <cuda_runtime.h>
#include <cstdint>

// Board: 64x64, 8 channels, channels-last float32. HW = 4096 cells.
// Persistent CTAs, grid-stride over boards, software-pipelined loads:
// board i+1's 16 LDG.128 are issued before board i's reduce/store phase.

#define HW_    4096
#define NT     256
#define CELLS  16        // HW_ / NT
#define NW     8         // warps per CTA
#define NB     4096      // batch
#define GRID   304       // 152 SMs * 2 CTAs

__device__ __forceinline__ void merge2min(float& m1, int& i1, float& m2,
                                          float m1b, int i1b, float m2b) {
    if (m1b < m1 || (m1b == m1 && i1b < i1)) {
        m2 = fminf(m1, m2b);
        m1 = m1b; i1 = i1b;
    } else {
        m2 = fminf(m2, m1b);
    }
}

__global__ __launch_bounds__(NT, 2)
void oracle_kernel(const float* __restrict__ x,
                   const float* __restrict__ opp_start,
                   float* __restrict__ out) {
    const int tid = threadIdx.x;
    const int wid = tid >> 5;
    const int lid = tid & 31;
    const float FINF = __int_as_float(0x7f800000);

    __shared__ int   s_nf[NW], s_no[NW], s_fo[NW], s_i1[NW];
    __shared__ float s_m1[NW], s_m2[NW];

    const float os0 = __ldg(&opp_start[0]);
    const float os1 = __ldg(&opp_start[1]);

    int board = blockIdx.x;

    // ---- prologue: issue loads for the first board ----
    float4 v[CELLS];
    {
        const float4* xb = reinterpret_cast<const float4*>(x) + (size_t)board * HW_ * 2;
#pragma unroll
        for (int k = 0; k < CELLS; k++)
            v[k] = xb[2 * (k * NT + tid)];
    }

    while (true) {
        const int cur = board;
        board += GRID;
        const bool more = (board < NB);

        // ---- consume v[] into compact masks (waits on in-flight loads) ----
        unsigned foodmask = 0;
        int nf = 0, no = 0;
        int fo = 1 << 30;
#pragma unroll
        for (int k = 0; k < CELLS; k++) {
            const int cell = k * NT + tid;
            const bool food = (v[k].y == 1.0f);
            const bool opp  = (v[k].w == 1.0f);
            foodmask |= (unsigned)food << k;
            nf += food;
            no += opp;
            if (opp && cell < fo) fo = cell;
        }

        // ---- immediately issue next board's loads (fill DRAM pipeline) ----
        if (more) {
            const float4* xb = reinterpret_cast<const float4*>(x) + (size_t)board * HW_ * 2;
#pragma unroll
            for (int k = 0; k < CELLS; k++)
                v[k] = xb[2 * (k * NT + tid)];
        }

        // ---- reductions for current board (loads for next are in flight) ----
        nf = __reduce_add_sync(0xffffffffu, nf);
        no = __reduce_add_sync(0xffffffffu, no);
        fo = __reduce_min_sync(0xffffffffu, fo);
        if (lid == 0) { s_nf[wid] = nf; s_no[wid] = no; s_fo[wid] = fo; }
        __syncthreads();

        int tot_nf = 0, tot_no = 0, tfo = 1 << 30;
#pragma unroll
        for (int w = 0; w < NW; w++) {
            tot_nf += s_nf[w];
            tot_no += s_no[w];
            tfo = min(tfo, s_fo[w]);
        }
        if (tfo == (1 << 30)) tfo = 0;   // argmax over all-False == 0
        const int orow = tfo >> 6;
        const int ocol = tfo & 63;

        // ---- two-smallest food distances ----
        float m1 = FINF, m2 = FINF;
        int   i1 = 0;
#pragma unroll
        for (int k = 0; k < CELLS; k++) {
            const int cell = k * NT + tid;
            if ((foodmask >> k) & 1u) {
                const int dr = (cell >> 6) - orow;
                const int dc = (cell & 63) - ocol;
                const float d = __fsqrt_rn((float)(dr * dr + dc * dc));
                if (d < m1) { m2 = m1; m1 = d; i1 = cell; }
                else        { m2 = fminf(m2, d); }
            }
        }
#pragma unroll
        for (int off = 16; off; off >>= 1) {
            const float m1b = __shfl_xor_sync(0xffffffffu, m1, off);
            const int   i1b = __shfl_xor_sync(0xffffffffu, i1, off);
            const float m2b = __shfl_xor_sync(0xffffffffu, m2, off);
            merge2min(m1, i1, m2, m1b, i1b, m2b);
        }
        if (lid == 0) { s_m1[wid] = m1; s_i1[wid] = i1; s_m2[wid] = m2; }
        __syncthreads();

        float M1 = s_m1[0], M2 = s_m2[0];
        int   I1 = s_i1[0];
#pragma unroll
        for (int w = 1; w < NW; w++)
            merge2min(M1, I1, M2, s_m1[w], s_i1[w], s_m2[w]);

        // ---- branch logic ----
        const bool matches_start = ((float)orow == os0) && ((float)ocol == os1);
        const bool branchA = (tot_nf > 1) && (tot_no > 0) && !matches_start;
        const float diff = M2 - M1;
        const bool ambiguous    = (branchA && (diff <  0.1f)) || ((tot_nf > 1) && !branchA);
        const bool pick_nearest = (branchA && (diff >= 0.1f)) || (tot_nf == 1);

        // ---- coalesced writeback ----
        float* ob = out + (size_t)cur * HW_;
#pragma unroll
        for (int k = 0; k < CELLS; k++) {
            const int cell = k * NT + tid;
            float hit;
            if (ambiguous)         hit = ((foodmask >> k) & 1u) ? 1.0f : 0.0f;
            else if (pick_nearest) hit = (cell == I1) ? 1.0f : 0.0f;
            else                   hit = 0.0f;
            ob[cell] = -10.0f + 20.0f * hit;
        }

        if (!more) break;
    }
}

extern "C" void kernel_launch(void* const* d_in, const int* in_sizes, int n_in,
                              void* d_out, int out_size) {
    const float* x         = (const float*)d_in[0];
    const float* opp_start = (const float*)d_in[1];
    float* out = (float*)d_out;

    oracle_kernel<<<GRID, NT>>>(x, opp_start, out);
}

// round 4
// speedup vs baseline: 1.0904x; 1.0904x over previous
#include <cuda_runtime.h>
#include <cstdint>

// Board: 64x64, 8 channels, channels-last float32. HW = 4096 cells.
// One CTA per batch element. 256 threads x 16 cells/thread.
// R4: 64-reg budget so all 16 LDG.128 front-batch; integer d^2 two-min pass.

#define HW_       4096
#define NTHREADS  256
#define CELLS     16
#define NW        8
#define IMAXS     0x7fffffff

__device__ __forceinline__ void merge2min_i(int& m1, int& i1, int& m2,
                                            int m1b, int i1b, int m2b) {
    // (smallest d^2, row-major argmin, second-smallest d^2)
    if (m1b < m1 || (m1b == m1 && i1b < i1)) {
        m2 = min(m1, m2b);
        m1 = m1b; i1 = i1b;
    } else {
        m2 = min(m2, m1b);
    }
}

__global__ __launch_bounds__(NTHREADS, 4)
void oracle_kernel(const float* __restrict__ x,
                   const float* __restrict__ opp_start,
                   float* __restrict__ out) {
    const int b   = blockIdx.x;
    const int tid = threadIdx.x;
    const int wid = tid >> 5;
    const int lid = tid & 31;

    // Each cell = 32 bytes; first float4 holds channels 0..3:
    // .y = channel 1 (food), .w = channel 3 (opp).
    const float4* xb = reinterpret_cast<const float4*>(x) + (size_t)b * HW_ * 2;

    // ---------------- Phase 1: front-batched loads ---------------------------
    float4 v[CELLS];
#pragma unroll
    for (int k = 0; k < CELLS; k++) {
        v[k] = xb[2 * (k * NTHREADS + tid)];
    }

    unsigned foodmask = 0;
    int nf = 0, no = 0;
    int fo = IMAXS;   // first-opp candidate (min row-major idx)
#pragma unroll
    for (int k = 0; k < CELLS; k++) {
        const int cell = k * NTHREADS + tid;
        const bool food = (v[k].y == 1.0f);
        const bool opp  = (v[k].w == 1.0f);
        foodmask |= (unsigned)food << k;
        nf += food;
        no += opp;
        if (opp && cell < fo) fo = cell;
    }

    nf = __reduce_add_sync(0xffffffffu, nf);
    no = __reduce_add_sync(0xffffffffu, no);
    fo = __reduce_min_sync(0xffffffffu, fo);

    __shared__ int s_nf[NW], s_no[NW], s_fo[NW], s_i1[NW], s_m1[NW], s_m2[NW];

    if (lid == 0) { s_nf[wid] = nf; s_no[wid] = no; s_fo[wid] = fo; }
    __syncthreads();

    int tot_nf = 0, tot_no = 0, tfo = IMAXS;
#pragma unroll
    for (int w = 0; w < NW; w++) {
        tot_nf += s_nf[w];
        tot_no += s_no[w];
        tfo = min(tfo, s_fo[w]);
    }
    if (tfo == IMAXS) tfo = 0;       // argmax over all-False == 0 (JAX semantics)
    const int orow = tfo >> 6;
    const int ocol = tfo & 63;

    // ---------------- Phase 2: two-smallest food d^2 (integer, exact) --------
    int m1 = IMAXS, m2 = IMAXS;
    int i1 = 0;                       // argmin over all-INF row == 0
#pragma unroll
    for (int k = 0; k < CELLS; k++) {
        const int cell = k * NTHREADS + tid;
        if ((foodmask >> k) & 1u) {
            const int dr = (cell >> 6) - orow;
            const int dc = (cell & 63) - ocol;
            const int d2 = dr * dr + dc * dc;
            if (d2 < m1) { m2 = m1; m1 = d2; i1 = cell; }
            else         { m2 = min(m2, d2); }
        }
    }

#pragma unroll
    for (int off = 16; off; off >>= 1) {
        const int m1b = __shfl_xor_sync(0xffffffffu, m1, off);
        const int i1b = __shfl_xor_sync(0xffffffffu, i1, off);
        const int m2b = __shfl_xor_sync(0xffffffffu, m2, off);
        merge2min_i(m1, i1, m2, m1b, i1b, m2b);
    }
    if (lid == 0) { s_m1[wid] = m1; s_i1[wid] = i1; s_m2[wid] = m2; }
    __syncthreads();

    int M1 = s_m1[0], M2 = s_m2[0], I1 = s_i1[0];
#pragma unroll
    for (int w = 1; w < NW; w++) {
        merge2min_i(M1, I1, M2, s_m1[w], s_i1[w], s_m2[w]);
    }

    // ---------------- Branch logic (redundant per thread) --------------------
    const float os0 = __ldg(&opp_start[0]);
    const float os1 = __ldg(&opp_start[1]);
    const bool matches_start = ((float)orow == os0) && ((float)ocol == os1);
    const bool branchA = (tot_nf > 1) && (tot_no > 0) && !matches_start;
    // diff only consumed when tot_nf > 1 (M1, M2 finite there); f32 sqrt of
    // exact ints matches reference bit-for-bit.
    const float diff = __fsqrt_rn((float)(M2 == IMAXS ? 0 : M2))
                     - __fsqrt_rn((float)(M1 == IMAXS ? 0 : M1));
    const bool ambiguous    = (branchA && (diff <  0.1f)) || ((tot_nf > 1) && !branchA);
    const bool pick_nearest = (branchA && (diff >= 0.1f)) || (tot_nf == 1);

    // ---------------- Writeback ----------------------------------------------
    float* ob = out + (size_t)b * HW_;
#pragma unroll
    for (int k = 0; k < CELLS; k++) {
        const int cell = k * NTHREADS + tid;
        const bool fbit = (foodmask >> k) & 1u;
        const bool hit = ambiguous ? fbit : (pick_nearest && (cell == I1));
        ob[cell] = hit ? 10.0f : -10.0f;
    }
}

extern "C" void kernel_launch(void* const* d_in, const int* in_sizes, int n_in,
                              void* d_out, int out_size) {
    const float* x         = (const float*)d_in[0];
    const float* opp_start = (const float*)d_in[1];
    float* out = (float*)d_out;

    const int B = in_sizes[0] / (HW_ * 8);   // 4096
    oracle_kernel<<<B, NTHREADS>>>(x, opp_start, out);
}